// round 12
// baseline (speedup 1.0000x reference)
#include <cuda_runtime.h>
#include <cuda_bf16.h>
#include <cstdint>

// Problem constants
#define M_ROWS 4096
#define K_DIM  256
#define NN     16384
#define KTOP   1638

// GEMM tiling: one 1024-thread CTA per 128x128 tile, full K resident.
#define TR 128
#define TC 128
#define GEMM_THREADS 1024            // 32 warps -> 8 warps/SMSP at 1 CTA/SM
#define SLOTS 64                     // per-column CSC capacity (max nnz ~48)
#define XS_STRIDE 132                // 132*4=528=33*16 -> LDS.128 16B-aligned
#define OS_STRIDE 129                // 129 % 32 == 1 -> conflict-free col stores

#define PP_OFF   (K_DIM * XS_STRIDE)            // float index of pair tile
#define SCNT_OFF (PP_OFF + SLOTS * TC * 2)      // float index of counts
#define GEMM_SMEM ((SCNT_OFF + TC) * 4)         // 201216 B -> 1 CTA/SM

// ---------------------------------------------------------------------------
// Scratch: CSC of W, [slot][n] layout (coalesced build writes AND gemm loads)
// pair = (w, k-as-float-bits). Tail slots zero-filled by build => inert FMA.
// ---------------------------------------------------------------------------
__device__ float2 g_pairT[(size_t)SLOTS * NN];   // 8.4 MB
__device__ int    g_cnt[NN];

// ---------------------------------------------------------------------------
// Kernel 1: build CSC (+ inline tail zero-fill). One thread per column;
// W reads and g_pairT writes both coalesced across adjacent n.
// ---------------------------------------------------------------------------
__global__ void __launch_bounds__(128) build_pack_kernel(const float* __restrict__ W) {
    const int n = blockIdx.x * blockDim.x + threadIdx.x;
    if (n >= NN) return;
    int c = 0;
    for (int k = 0; k < K_DIM; ++k) {
        const float w = W[(size_t)k * NN + n];
        if (w != 0.0f) {
            if (c < SLOTS) g_pairT[(size_t)c * NN + n] = make_float2(w, __int_as_float(k));
            ++c;
        }
    }
    const int cc = (c < SLOTS) ? c : SLOTS;
    for (int s = cc; s < SLOTS; ++s)
        g_pairT[(size_t)s * NN + n] = make_float2(0.f, 0.f);
    g_cnt[n] = cc;
}

// ---------------------------------------------------------------------------
// Kernel 2: sparse GEMM  out = relu(x @ W + bias), dense output.
// 1024 threads / 32 warps; warp owns 4 columns, lane owns 4 consecutive rows
// (float4 from smem x-tile). Pair lists staged in SMEM; in-loop pair reads
// are warp-uniform LDS.64 broadcasts. acc = 4 float4 = 16 regs.
// ---------------------------------------------------------------------------
__global__ void __launch_bounds__(GEMM_THREADS, 1) gemm_kernel(
    const float* __restrict__ x,
    const float* __restrict__ bias,
    float* __restrict__ out)
{
    extern __shared__ float sm[];
    float*  xs    = sm;                          // [K_DIM][XS_STRIDE]
    float2* ppair = (float2*)(sm + PP_OFF);      // [SLOTS][TC]
    int*    scnt  = (int*)(sm + SCNT_OFF);       // [TC] padded counts

    const int row0 = blockIdx.y * TR;
    const int col0 = blockIdx.x * TC;
    const int tid  = threadIdx.x;

    // fill x tile transposed: xs[k][r]  (gmem coalesced)
    for (int u = tid; u < TR * K_DIM; u += GEMM_THREADS) {
        const int r = u >> 8;                // 0..127
        const int k = u & 255;               // 0..255
        xs[k * XS_STRIDE + r] = x[(size_t)(row0 + r) * K_DIM + k];
    }
    // fill pair tile: ppair[s][c] <- g_pairT[s][col0+c]  (LDG.64 coalesced)
    for (int u = tid; u < SLOTS * TC; u += GEMM_THREADS) {
        const int s = u >> 7;                // slot
        const int c = u & 127;               // col in tile
        ppair[s * TC + c] = g_pairT[(size_t)s * NN + col0 + c];
    }
    if (tid < TC) scnt[tid] = (g_cnt[col0 + tid] + 7) & ~7;   // pad to 8
    __syncthreads();

    const int warp  = tid >> 5;              // 0..31
    const int lane  = tid & 31;
    const int rbase = lane << 2;

    float4 acc[4];
#pragma unroll
    for (int cc = 0; cc < 4; ++cc) {
        const int c = (warp << 2) + cc;
        const int cntp = scnt[c];
        const float2* pp = ppair + c;
        float4 a = make_float4(0.f, 0.f, 0.f, 0.f);
        for (int j = 0; j < cntp; j += 8) {  // tail slots zero => inert
#pragma unroll
            for (int u = 0; u < 8; ++u) {
                const float2 p = pp[(j + u) * TC];              // broadcast
                const int    k = __float_as_int(p.y);
                const float4 xv = *(const float4*)(xs + k * XS_STRIDE + rbase);
                a.x = fmaf(xv.x, p.x, a.x);
                a.y = fmaf(xv.y, p.x, a.y);
                a.z = fmaf(xv.z, p.x, a.z);
                a.w = fmaf(xv.w, p.x, a.w);
            }
        }
        const float b = __ldg(bias + col0 + c);
        a.x = fmaxf(a.x + b, 0.f);
        a.y = fmaxf(a.y + b, 0.f);
        a.z = fmaxf(a.z + b, 0.f);
        a.w = fmaxf(a.w + b, 0.f);
        acc[cc] = a;
    }
    __syncthreads();                         // xs/ppair reads done -> reuse

    float* os = sm;                          // [TR][OS_STRIDE], overlays xs
#pragma unroll
    for (int cc = 0; cc < 4; ++cc) {
        const int c = (warp << 2) + cc;
        os[(rbase + 0) * OS_STRIDE + c] = acc[cc].x;
        os[(rbase + 1) * OS_STRIDE + c] = acc[cc].y;
        os[(rbase + 2) * OS_STRIDE + c] = acc[cc].z;
        os[(rbase + 3) * OS_STRIDE + c] = acc[cc].w;
    }
    __syncthreads();

    // flush tile, scalar + coalesced (consecutive threads -> consecutive cols)
    for (int l = tid; l < TR * TC; l += GEMM_THREADS) {
        const int r = l >> 7;
        const int c = l & 127;
        out[(size_t)(row0 + r) * NN + col0 + c] = os[r * OS_STRIDE + c];
    }
}

// ---------------------------------------------------------------------------
// Kernel 3: per-row exact top-K, 3 gmem reads + 1 write.
// Pass1: 12-bit histogram (bits[31:20], 4096 shared bins; zeros aggregated).
// Pass2: compact candidates in the threshold bin into smem; exact threshold
// + tie resolution on the small candidate list. Pass3: masked write-back.
// relu => all >= 0 => uint compare is order-preserving.
// ---------------------------------------------------------------------------
#define CAP 2048

__global__ void __launch_bounds__(256) topk_kernel(float* __restrict__ out) {
    __shared__ int hist[4096];
    __shared__ unsigned int candv[CAP];
    __shared__ int candi[CAP];
    __shared__ int chunksum[256];
    __shared__ int eqix[512];
    __shared__ int s_b1, s_krem, s_cnt, s_need, s_m, s_eqcnt;
    __shared__ unsigned int s_tbits;

    const int t = threadIdx.x;
    const int lane = t & 31;
    float* rp = out + (size_t)blockIdx.x * NN;
    const uint4* rp4 = (const uint4*)rp;

    for (int i = t; i < 4096; i += 256) hist[i] = 0;
    if (t == 0) { s_cnt = 0; s_eqcnt = 0; }
    __syncthreads();

    // ---- pass 1: 12-bit histogram ----
    {
        int zc = 0;
        for (int i = t; i < NN / 4; i += 256) {
            const uint4 q = rp4[i];
            if (q.x) atomicAdd(&hist[q.x >> 20], 1); else ++zc;
            if (q.y) atomicAdd(&hist[q.y >> 20], 1); else ++zc;
            if (q.z) atomicAdd(&hist[q.z >> 20], 1); else ++zc;
            if (q.w) atomicAdd(&hist[q.w >> 20], 1); else ++zc;
        }
#pragma unroll
        for (int off = 16; off; off >>= 1) zc += __shfl_down_sync(0xffffffffu, zc, off);
        if (lane == 0 && zc) atomicAdd(&hist[0], zc);
    }
    __syncthreads();
    { int s = 0; for (int k = 0; k < 16; ++k) s += hist[t * 16 + k]; chunksum[t] = s; }
    __syncthreads();
    if (t == 0) {
        int kr = KTOP, c = 255;
        for (;; --c) { const int h = chunksum[c]; if (h >= kr) break; kr -= h; }
        int b = c * 16 + 15;
        for (;; --b) { const int h = hist[b]; if (h >= kr) break; kr -= h; }
        s_b1 = b; s_krem = kr;
    }
    __syncthreads();
    const int b1 = s_b1;
    const int krem = s_krem;

    unsigned int tbits = 0u;
    int need = 0, m = 0;
    bool keep_all = true;

    if (b1 != 0) {
        // ---- pass 2: compact threshold-bin candidates ----
        for (int i = t; i < NN / 4; i += 256) {
            const uint4 q = rp4[i];
            const int base = i * 4;
            if ((int)(q.x >> 20) == b1) { const int p = atomicAdd(&s_cnt, 1); if (p < CAP) { candv[p] = q.x; candi[p] = base + 0; } }
            if ((int)(q.y >> 20) == b1) { const int p = atomicAdd(&s_cnt, 1); if (p < CAP) { candv[p] = q.y; candi[p] = base + 1; } }
            if ((int)(q.z >> 20) == b1) { const int p = atomicAdd(&s_cnt, 1); if (p < CAP) { candv[p] = q.z; candi[p] = base + 2; } }
            if ((int)(q.w >> 20) == b1) { const int p = atomicAdd(&s_cnt, 1); if (p < CAP) { candv[p] = q.w; candi[p] = base + 3; } }
        }
        __syncthreads();
        const int cnt = s_cnt;
        if (cnt > CAP) {
            // practically unreachable fallback: keep the whole bin
            tbits = ((unsigned int)b1 << 20) - 1u;
            keep_all = true;
        } else {
            // exact krem-th largest among candidates (O(cnt^2/256) smem work)
            for (int i = t; i < cnt; i += 256) {
                const unsigned int u = candv[i];
                int g = 0, e = 0;
                for (int j = 0; j < cnt; ++j) {
                    const unsigned int v = candv[j];
                    g += (v > u); e += (v == u);
                }
                if (g < krem && krem <= g + e) { s_tbits = u; s_need = krem - g; s_m = e; }
            }
            __syncthreads();
            tbits = s_tbits; need = s_need; m = s_m;
            keep_all = (need >= m) || (m > 512);
            if (!keep_all) {
                for (int i = t; i < cnt; i += 256)
                    if (candv[i] == tbits) { const int p = atomicAdd(&s_eqcnt, 1); if (p < 512) eqix[p] = candi[i]; }
                __syncthreads();
            }
        }
    }
    // b1 == 0: tbits stays 0 -> keep all positives (kept "zeros" write 0 anyway)

    // ---- pass 3: masked write-back ----
    uint4* wp4 = (uint4*)rp;
    for (int i = t; i < NN / 4; i += 256) {
        uint4 q = rp4[i];
        const int base = i * 4;
        unsigned int* pc = (unsigned int*)&q;
#pragma unroll
        for (int c = 0; c < 4; ++c) {
            const unsigned int u = pc[c];
            unsigned int r = 0u;
            if (u > tbits) {
                r = u;
            } else if (u == tbits && tbits != 0u) {
                if (keep_all) {
                    r = u;
                } else {
                    int rank = 0;
                    for (int qq = 0; qq < m; ++qq) rank += (eqix[qq] < base + c);
                    if (rank < need) r = u;
                }
            }
            pc[c] = r;
        }
        wp4[i] = q;
    }
}

// ---------------------------------------------------------------------------
// Launch
// ---------------------------------------------------------------------------
extern "C" void kernel_launch(void* const* d_in, const int* in_sizes, int n_in,
                              void* d_out, int out_size)
{
    const float* x = nullptr;
    const float* W = nullptr;
    const float* bias = nullptr;
    for (int i = 0; i < n_in; ++i) {
        if (in_sizes[i] == M_ROWS * K_DIM)      x = (const float*)d_in[i];
        else if (in_sizes[i] == K_DIM * NN)     W = (const float*)d_in[i];
        else if (in_sizes[i] == NN)             bias = (const float*)d_in[i];
    }
    float* out = (float*)d_out;

    cudaFuncSetAttribute(gemm_kernel, cudaFuncAttributeMaxDynamicSharedMemorySize, GEMM_SMEM);

    build_pack_kernel<<<NN / 128, 128>>>(W);

    dim3 ggrid(NN / TC, M_ROWS / TR);        // 128 x 32 = 4096 tiles
    gemm_kernel<<<ggrid, GEMM_THREADS, GEMM_SMEM>>>(x, bias, out);

    topk_kernel<<<M_ROWS, 256>>>(out);
}

// round 13
// speedup vs baseline: 1.0730x; 1.0730x over previous
#include <cuda_runtime.h>
#include <cuda_bf16.h>
#include <cstdint>

// Problem constants
#define M_ROWS 4096
#define K_DIM  256
#define NN     16384
#define KTOP   1638

// GEMM tiling (R9 structure: 512 threads, full K, 1 CTA/SM)
#define TR 128
#define TC 128
#define GEMM_THREADS 512
#define SLOTS 64                     // per-column CSC capacity (max nnz ~48)
#define NQ (SLOTS / 2)               // 32 quads (2 pairs each)
#define XS_STRIDE 132                // 132*4=528=33*16 -> LDS.128 16B-aligned
#define OS_STRIDE 129                // conflict-free column stores

#define PP_OFF   (K_DIM * XS_STRIDE)            // 33792 floats; *4 % 16 == 0
#define SCNT_OFF (PP_OFF + NQ * TC * 4)         // + 16384 floats (64 KB quads)
#define GEMM_SMEM ((SCNT_OFF + TC) * 4)         // 201216 B -> 1 CTA/SM

// ---------------------------------------------------------------------------
// Scratch: quad-packed CSC of W, [quad][n] layout (coalesced everywhere).
// quad = (w0, k0-as-float-bits, w1, k1-as-float-bits). Tail zeroed => inert.
// ---------------------------------------------------------------------------
__device__ float4 g_pairQ[(size_t)NQ * NN];      // 8.4 MB
__device__ int    g_cnt[NN];

// ---------------------------------------------------------------------------
// Kernel 1: build quad CSC (+ inline tail zero-fill). One thread per column;
// W reads and g_pairQ writes both coalesced across adjacent n.
// ---------------------------------------------------------------------------
__global__ void __launch_bounds__(128) build_pack_kernel(const float* __restrict__ W) {
    const int n = blockIdx.x * blockDim.x + threadIdx.x;
    if (n >= NN) return;
    float4 quad = make_float4(0.f, 0.f, 0.f, 0.f);
    int c = 0;
    for (int k = 0; k < K_DIM; ++k) {
        const float w = W[(size_t)k * NN + n];
        if (w != 0.0f && c < SLOTS) {
            if ((c & 1) == 0) { quad.x = w; quad.y = __int_as_float(k); }
            else {
                quad.z = w; quad.w = __int_as_float(k);
                g_pairQ[(size_t)(c >> 1) * NN + n] = quad;
                quad = make_float4(0.f, 0.f, 0.f, 0.f);
            }
            ++c;
        }
    }
    int q = c >> 1;
    if (c & 1) { g_pairQ[(size_t)q * NN + n] = quad; ++q; }
    for (; q < NQ; ++q)
        g_pairQ[(size_t)q * NN + n] = make_float4(0.f, 0.f, 0.f, 0.f);
    g_cnt[n] = c;
}

// ---------------------------------------------------------------------------
// Kernel 2: sparse GEMM  out = relu(x @ W + bias), dense output.
// 512 threads / 16 warps; warp owns 8 columns, lane owns 4 consecutive rows
// (float4 from smem x-tile). Quad lists staged in SMEM; in-loop reads are
// warp-uniform LDS.128 broadcasts carrying TWO (w,k) pairs each.
// ---------------------------------------------------------------------------
__global__ void __launch_bounds__(GEMM_THREADS, 1) gemm_kernel(
    const float* __restrict__ x,
    const float* __restrict__ bias,
    float* __restrict__ out)
{
    extern __shared__ float sm[];
    float*  xs  = sm;                            // [K_DIM][XS_STRIDE]
    float4* ppq = (float4*)(sm + PP_OFF);        // [NQ][TC]
    int*    scnt = (int*)(sm + SCNT_OFF);        // [TC] padded counts

    const int row0 = blockIdx.y * TR;
    const int col0 = blockIdx.x * TC;
    const int tid  = threadIdx.x;

    // fill x tile transposed: xs[k][r]  (gmem coalesced)
    for (int u = tid; u < TR * K_DIM; u += GEMM_THREADS) {
        const int r = u >> 8;                // 0..127
        const int k = u & 255;               // 0..255
        xs[k * XS_STRIDE + r] = x[(size_t)(row0 + r) * K_DIM + k];
    }
    // fill quad tile: ppq[q][c] <- g_pairQ[q][col0+c]  (LDG.128 coalesced)
    for (int u = tid; u < NQ * TC; u += GEMM_THREADS) {
        const int q = u >> 7;
        const int c = u & 127;
        ppq[q * TC + c] = g_pairQ[(size_t)q * NN + col0 + c];
    }
    if (tid < TC) scnt[tid] = (g_cnt[col0 + tid] + 7) & ~7;   // pad to 8
    __syncthreads();

    const int warp  = tid >> 5;              // 0..15
    const int lane  = tid & 31;
    const int rbase = lane << 2;

    float4 acc[8];
#pragma unroll
    for (int cc = 0; cc < 8; ++cc) {
        const int c = (warp << 3) + cc;
        const int cntp = scnt[c];
        const float4* pq = ppq + c;
        float4 a = make_float4(0.f, 0.f, 0.f, 0.f);
        for (int j = 0; j < cntp; j += 8) {  // tail slots zero => inert
            const int sp = j >> 1;
            const float4 q0 = pq[(sp + 0) * TC];
            const float4 q1 = pq[(sp + 1) * TC];
            const float4 q2 = pq[(sp + 2) * TC];
            const float4 q3 = pq[(sp + 3) * TC];
            {
                const float4 xv = *(const float4*)(xs + __float_as_int(q0.y) * XS_STRIDE + rbase);
                a.x = fmaf(xv.x, q0.x, a.x); a.y = fmaf(xv.y, q0.x, a.y);
                a.z = fmaf(xv.z, q0.x, a.z); a.w = fmaf(xv.w, q0.x, a.w);
            }
            {
                const float4 xv = *(const float4*)(xs + __float_as_int(q0.w) * XS_STRIDE + rbase);
                a.x = fmaf(xv.x, q0.z, a.x); a.y = fmaf(xv.y, q0.z, a.y);
                a.z = fmaf(xv.z, q0.z, a.z); a.w = fmaf(xv.w, q0.z, a.w);
            }
            {
                const float4 xv = *(const float4*)(xs + __float_as_int(q1.y) * XS_STRIDE + rbase);
                a.x = fmaf(xv.x, q1.x, a.x); a.y = fmaf(xv.y, q1.x, a.y);
                a.z = fmaf(xv.z, q1.x, a.z); a.w = fmaf(xv.w, q1.x, a.w);
            }
            {
                const float4 xv = *(const float4*)(xs + __float_as_int(q1.w) * XS_STRIDE + rbase);
                a.x = fmaf(xv.x, q1.z, a.x); a.y = fmaf(xv.y, q1.z, a.y);
                a.z = fmaf(xv.z, q1.z, a.z); a.w = fmaf(xv.w, q1.z, a.w);
            }
            {
                const float4 xv = *(const float4*)(xs + __float_as_int(q2.y) * XS_STRIDE + rbase);
                a.x = fmaf(xv.x, q2.x, a.x); a.y = fmaf(xv.y, q2.x, a.y);
                a.z = fmaf(xv.z, q2.x, a.z); a.w = fmaf(xv.w, q2.x, a.w);
            }
            {
                const float4 xv = *(const float4*)(xs + __float_as_int(q2.w) * XS_STRIDE + rbase);
                a.x = fmaf(xv.x, q2.z, a.x); a.y = fmaf(xv.y, q2.z, a.y);
                a.z = fmaf(xv.z, q2.z, a.z); a.w = fmaf(xv.w, q2.z, a.w);
            }
            {
                const float4 xv = *(const float4*)(xs + __float_as_int(q3.y) * XS_STRIDE + rbase);
                a.x = fmaf(xv.x, q3.x, a.x); a.y = fmaf(xv.y, q3.x, a.y);
                a.z = fmaf(xv.z, q3.x, a.z); a.w = fmaf(xv.w, q3.x, a.w);
            }
            {
                const float4 xv = *(const float4*)(xs + __float_as_int(q3.w) * XS_STRIDE + rbase);
                a.x = fmaf(xv.x, q3.z, a.x); a.y = fmaf(xv.y, q3.z, a.y);
                a.z = fmaf(xv.z, q3.z, a.z); a.w = fmaf(xv.w, q3.z, a.w);
            }
        }
        const float b = __ldg(bias + col0 + c);
        a.x = fmaxf(a.x + b, 0.f);
        a.y = fmaxf(a.y + b, 0.f);
        a.z = fmaxf(a.z + b, 0.f);
        a.w = fmaxf(a.w + b, 0.f);
        acc[cc] = a;
    }
    __syncthreads();                         // xs/ppq reads done -> reuse

    float* os = sm;                          // [TR][OS_STRIDE], overlays xs
#pragma unroll
    for (int cc = 0; cc < 8; ++cc) {
        const int c = (warp << 3) + cc;
        os[(rbase + 0) * OS_STRIDE + c] = acc[cc].x;
        os[(rbase + 1) * OS_STRIDE + c] = acc[cc].y;
        os[(rbase + 2) * OS_STRIDE + c] = acc[cc].z;
        os[(rbase + 3) * OS_STRIDE + c] = acc[cc].w;
    }
    __syncthreads();

    // flush tile, scalar + coalesced (consecutive threads -> consecutive cols)
    for (int l = tid; l < TR * TC; l += GEMM_THREADS) {
        const int r = l >> 7;
        const int c = l & 127;
        out[(size_t)(row0 + r) * NN + col0 + c] = os[r * OS_STRIDE + c];
    }
}

// ---------------------------------------------------------------------------
// Kernel 3: per-row exact top-K — R9's measured-245us 4-pass version,
// verbatim. Radix select on float bits (relu => uint order-preserving),
// in-place, no row cache (L2-resident between passes), ~19KB static smem.
// ---------------------------------------------------------------------------
__global__ void __launch_bounds__(256) topk_kernel(float* __restrict__ out) {
    __shared__ int hist[4096];        // pass1: 8x256 warp-private; p2:2048; p3:4096
    __shared__ int eqix[512];
    __shared__ int chunksum[256];
    __shared__ int s_b1, s_b2, s_b3, s_krem, s_eqcnt;

    const int t = threadIdx.x;
    const int warp = t >> 5, lane = t & 31;
    float* rp = out + (size_t)blockIdx.x * NN;
    const uint4* rp4 = (const uint4*)rp;

    // ---- pass 1: bits [31:23], warp-private 256-bin hists ----
    for (int i = t; i < 2048; i += 256) hist[i] = 0;
    __syncthreads();
    {
        int* h1 = hist + warp * 256;
        int zc = 0;
        for (int i = t; i < NN / 4; i += 256) {
            const uint4 q = rp4[i];
            if (q.x) atomicAdd(&h1[q.x >> 23], 1); else ++zc;
            if (q.y) atomicAdd(&h1[q.y >> 23], 1); else ++zc;
            if (q.z) atomicAdd(&h1[q.z >> 23], 1); else ++zc;
            if (q.w) atomicAdd(&h1[q.w >> 23], 1); else ++zc;
        }
#pragma unroll
        for (int off = 16; off; off >>= 1) zc += __shfl_down_sync(0xffffffffu, zc, off);
        if (lane == 0 && zc) atomicAdd(&h1[0], zc);
    }
    __syncthreads();
    {
        int s = 0;
        for (int w = 0; w < 8; ++w) s += hist[w * 256 + t];
        chunksum[t] = s;
    }
    __syncthreads();
    if (t == 0) {
        int kr = KTOP, b = 255;
        for (;; --b) { const int h = chunksum[b]; if (h >= kr) break; kr -= h; }
        s_b1 = b; s_krem = kr;
    }
    __syncthreads();
    const unsigned int b1 = (unsigned int)s_b1;

    // ---- pass 2: bits [22:12] (2048 bins) among prefix matches ----
    for (int i = t; i < 2048; i += 256) hist[i] = 0;
    __syncthreads();
    for (int i = t; i < NN / 4; i += 256) {
        const uint4 q = rp4[i];
        if ((q.x >> 23) == b1) atomicAdd(&hist[(q.x >> 12) & 2047], 1);
        if ((q.y >> 23) == b1) atomicAdd(&hist[(q.y >> 12) & 2047], 1);
        if ((q.z >> 23) == b1) atomicAdd(&hist[(q.z >> 12) & 2047], 1);
        if ((q.w >> 23) == b1) atomicAdd(&hist[(q.w >> 12) & 2047], 1);
    }
    __syncthreads();
    { int s = 0; for (int k = 0; k < 8; ++k) s += hist[t * 8 + k]; chunksum[t] = s; }
    __syncthreads();
    if (t == 0) {
        int kr = s_krem, c = 255;
        for (;; --c) { const int h = chunksum[c]; if (h >= kr) break; kr -= h; }
        int b = c * 8 + 7;
        for (;; --b) { const int h = hist[b]; if (h >= kr) break; kr -= h; }
        s_b2 = b; s_krem = kr;
    }
    __syncthreads();
    const unsigned int pfx2 = (b1 << 11) | (unsigned int)s_b2;

    // ---- pass 3: bits [11:0] (4096 bins) ----
    for (int i = t; i < 4096; i += 256) hist[i] = 0;
    __syncthreads();
    for (int i = t; i < NN / 4; i += 256) {
        const uint4 q = rp4[i];
        if ((q.x >> 12) == pfx2) atomicAdd(&hist[q.x & 4095], 1);
        if ((q.y >> 12) == pfx2) atomicAdd(&hist[q.y & 4095], 1);
        if ((q.z >> 12) == pfx2) atomicAdd(&hist[q.z & 4095], 1);
        if ((q.w >> 12) == pfx2) atomicAdd(&hist[q.w & 4095], 1);
    }
    __syncthreads();
    { int s = 0; for (int k = 0; k < 16; ++k) s += hist[t * 16 + k]; chunksum[t] = s; }
    __syncthreads();
    if (t == 0) {
        int kr = s_krem, c = 255;
        for (;; --c) { const int h = chunksum[c]; if (h >= kr) break; kr -= h; }
        int b = c * 16 + 15;
        for (;; --b) { const int h = hist[b]; if (h >= kr) break; kr -= h; }
        s_b3 = b; s_krem = kr;        // kr = # of elements == threshold to KEEP
        s_eqcnt = 0;
    }
    __syncthreads();

    const unsigned int tbits = (pfx2 << 12) | (unsigned int)s_b3;
    const int need = s_krem;
    const int m    = hist[s_b3];
    const bool keep_all_eq = (need >= m) || (m > 512);

    // exact tie ranking (lowest indices first) — rare path
    if (tbits != 0u && !keep_all_eq) {
        const unsigned int* rpu = (const unsigned int*)rp;
        for (int i = t; i < NN; i += 256)
            if (rpu[i] == tbits) { const int p = atomicAdd(&s_eqcnt, 1); eqix[p] = i; }
        __syncthreads();
    }

    // write masked row back
    uint4* wp4 = (uint4*)rp;
    for (int i = t; i < NN / 4; i += 256) {
        uint4 q = rp4[i];
        const int base = i * 4;
        unsigned int* pc = (unsigned int*)&q;
#pragma unroll
        for (int c = 0; c < 4; ++c) {
            const unsigned int u = pc[c];
            unsigned int r = 0u;
            if (u > tbits) {
                r = u;
            } else if (u == tbits && tbits != 0u) {
                if (keep_all_eq) {
                    r = u;
                } else {
                    int rank = 0;
                    for (int qq = 0; qq < m; ++qq) rank += (eqix[qq] < base + c);
                    if (rank < need) r = u;
                }
            }
            pc[c] = r;
        }
        wp4[i] = q;
    }
}

// ---------------------------------------------------------------------------
// Launch
// ---------------------------------------------------------------------------
extern "C" void kernel_launch(void* const* d_in, const int* in_sizes, int n_in,
                              void* d_out, int out_size)
{
    const float* x = nullptr;
    const float* W = nullptr;
    const float* bias = nullptr;
    for (int i = 0; i < n_in; ++i) {
        if (in_sizes[i] == M_ROWS * K_DIM)      x = (const float*)d_in[i];
        else if (in_sizes[i] == K_DIM * NN)     W = (const float*)d_in[i];
        else if (in_sizes[i] == NN)             bias = (const float*)d_in[i];
    }
    float* out = (float*)d_out;

    cudaFuncSetAttribute(gemm_kernel, cudaFuncAttributeMaxDynamicSharedMemorySize, GEMM_SMEM);

    build_pack_kernel<<<NN / 128, 128>>>(W);

    dim3 ggrid(NN / TC, M_ROWS / TR);        // 128 x 32 = 4096 tiles
    gemm_kernel<<<ggrid, GEMM_THREADS, GEMM_SMEM>>>(x, bias, out);

    topk_kernel<<<M_ROWS, 256>>>(out);
}